// round 4
// baseline (speedup 1.0000x reference)
#include <cuda_runtime.h>
#include <cstddef>

#define VOCABP 50001
#define EMB    200
#define HID    128
#define BATCH  256
#define TSTEPS 500
#define NC     6
#define DENSE  64
#define NGATE  512   // 4*HID
#define HOFF   203   // row offset of h-part inside W [331, 512]

#define SMEM_COLS 416                 // gate columns cached in SMEM (13 warps)
#define TAILC     (NGATE - SMEM_COLS) // 96 columns streamed from L2
#define WPITCH    132                 // smem weight pitch in floats (528B: f4-aligned, phase-conflict-free)
#define GPITCH    516                 // gate staging pitch
#define SCAN_SMEM_BYTES ((SMEM_COLS*WPITCH + 4*HID + 4*GPITCH) * 4)

// ---------------- scratch (no allocations allowed) ----------------
__device__ float g_tab[2ull * VOCABP * NGATE];   // projected vocab tables, ~205 MB
__device__ float g_captab[2 * 4 * NGATE];        // cap one-hot projection + bias
__device__ float g_wtail[2 * TAILC * HID];       // transposed W_h tail cols [d][c][k]
__device__ float g_hfinal[2 * BATCH * HID];      // final hidden states per direction

__device__ __forceinline__ float sigf(float x) { return 1.0f / (1.0f + __expf(-x)); }
__device__ __forceinline__ float tanh_fast(float x) {
    return 1.0f - 2.0f / (__expf(2.0f * x) + 1.0f);
}

// packed fp32x2 FMA: d.lo += a.lo*b.lo ; d.hi += a.hi*b.hi
__device__ __forceinline__ void ffma2(unsigned long long& d,
                                      unsigned long long a, unsigned long long b) {
    asm("fma.rn.f32x2 %0, %1, %2, %0;" : "+l"(d) : "l"(a), "l"(b));
}
__device__ __forceinline__ float2 ull2f2(unsigned long long v) {
    float2 r; asm("mov.b64 {%0,%1}, %2;" : "=f"(r.x), "=f"(r.y) : "l"(v)); return r;
}
__device__ __forceinline__ unsigned long long fdup(float w) {
    unsigned long long r; asm("mov.b64 %0, {%1,%1};" : "=l"(r) : "f"(w)); return r;
}

// ---------------- kernel 1: Tab[d] = word_emb @ W_d[0:200,:] ----------------
__global__ void __launch_bounds__(512) tab_kernel(const float* __restrict__ emb,
                                                  const float* __restrict__ Wfw,
                                                  const float* __restrict__ Wbw)
{
    __shared__ float es[EMB * 16];   // [k][r] transposed tile, 12.8 KB
    const int d  = blockIdx.y;
    const int v0 = blockIdx.x * 16;
    const float* __restrict__ W = d ? Wbw : Wfw;
    const int tid = threadIdx.x;

    for (int i = tid; i < 16 * EMB; i += 512) {
        int r = i / EMB, k = i % EMB;
        int v = v0 + r;
        es[k * 16 + r] = (v < VOCABP) ? emb[(size_t)v * EMB + k] : 0.0f;
    }
    __syncthreads();

    const int c = tid;   // gate column 0..511
    unsigned long long acc[8];  // 8 packed pairs = 16 rows
#pragma unroll
    for (int p = 0; p < 8; p++) acc[p] = 0ull;

#pragma unroll 4
    for (int k = 0; k < EMB; k++) {
        unsigned long long wd = fdup(__ldg(&W[k * NGATE + c]));
        const ulonglong2* e2 = (const ulonglong2*)&es[k * 16];
        ulonglong2 ea = e2[0], eb = e2[1], ec = e2[2], ed = e2[3];
        ffma2(acc[0], ea.x, wd); ffma2(acc[1], ea.y, wd);
        ffma2(acc[2], eb.x, wd); ffma2(acc[3], eb.y, wd);
        ffma2(acc[4], ec.x, wd); ffma2(acc[5], ec.y, wd);
        ffma2(acc[6], ed.x, wd); ffma2(acc[7], ed.y, wd);
    }

    float* out = &g_tab[((size_t)d * VOCABP + v0) * NGATE + c];
#pragma unroll
    for (int p = 0; p < 8; p++) {
        float2 f = ull2f2(acc[p]);
        if (v0 + 2 * p     < VOCABP) out[(size_t)(2 * p)     * NGATE] = f.x;
        if (v0 + 2 * p + 1 < VOCABP) out[(size_t)(2 * p + 1) * NGATE] = f.y;
    }
}

// ---------------- kernel 2a: cap table (+ bias folded in) ----------------
__global__ void captab_kernel(const float* __restrict__ cemb,
                              const float* __restrict__ Wfw, const float* __restrict__ bfw,
                              const float* __restrict__ Wbw, const float* __restrict__ bbw)
{
    int idx = blockIdx.x * blockDim.x + threadIdx.x;
    if (idx >= 2 * 4 * NGATE) return;
    int d  = idx / (4 * NGATE);
    int ci = (idx / NGATE) & 3;
    int c  = idx % NGATE;
    const float* W = d ? Wbw : Wfw;
    const float* b = d ? bbw : bfw;
    float v = b[c];
#pragma unroll
    for (int j = 0; j < 3; j++) v += cemb[ci * 3 + j] * W[(EMB + j) * NGATE + c];
    g_captab[idx] = v;
}

// ---------------- kernel 2b: transpose tail W_h columns into g_wtail ----------------
__global__ void wtail_kernel(const float* __restrict__ Wfw, const float* __restrict__ Wbw)
{
    int idx = blockIdx.x * blockDim.x + threadIdx.x;
    if (idx >= 2 * TAILC * HID) return;
    int d  = idx / (TAILC * HID);
    int ct = (idx / HID) % TAILC;
    int k  = idx % HID;
    const float* W = d ? Wbw : Wfw;
    g_wtail[idx] = W[(HOFF + k) * NGATE + SMEM_COLS + ct];
}

// ---------------- kernel 3: the recurrent scan ----------------
// grid = 128 CTAs: blockIdx.x>>6 = direction, (blockIdx.x&63)*4 = first batch row
// 512 threads: thread c computes gate column c for 4 batch rows.
__global__ void __launch_bounds__(512, 1) scan_kernel(const int* __restrict__ words,
                                                      const int* __restrict__ caps,
                                                      const float* __restrict__ Wfw,
                                                      const float* __restrict__ Wbw)
{
    extern __shared__ float sm[];
    float* Ws  = sm;                        // [SMEM_COLS][WPITCH]  ~219.6 KB, transposed
    float* h_s = Ws + SMEM_COLS * WPITCH;   // [4][HID]
    float* g_s = h_s + 4 * HID;             // [4][GPITCH]

    const int tid = threadIdx.x;
    const int d   = blockIdx.x >> 6;
    const int b0  = (blockIdx.x & 63) * 4;
    const float* __restrict__ W = d ? Wbw : Wfw;

    // stage W_h columns [0, SMEM_COLS) transposed: Ws[c][k]
    for (int i = tid; i < HID * SMEM_COLS; i += 512) {
        int k = i / SMEM_COLS, c = i % SMEM_COLS;   // coalesced global read
        Ws[c * WPITCH + k] = W[(HOFF + k) * NGATE + c];
    }
    if (tid < 4 * HID) h_s[tid] = 0.0f;

    const int r_id = tid >> 7;     // gate-update mapping: row
    const int u    = tid & 127;    // hidden unit
    float cst = 0.0f;              // cell state lives in registers
    float hh  = 0.0f;

    const int c = tid;             // gate column
    const float* __restrict__ tabd  = &g_tab[(size_t)d * VOCABP * NGATE];
    const float* __restrict__ capd  = &g_captab[d * 4 * NGATE];
    const float* __restrict__ wcs   = &Ws[c * WPITCH];                        // smem path
    const float* __restrict__ wct   = &g_wtail[(d * TAILC + (c - SMEM_COLS)) * HID]; // tail path

    __syncthreads();

    // prefetch indices for t = 0
    int widx[4], cidx[4];
    {
        int t0 = d ? (TSTEPS - 1) : 0;
#pragma unroll
        for (int r = 0; r < 4; r++) {
            widx[r] = __ldg(&words[(b0 + r) * TSTEPS + t0]);
            cidx[r] = __ldg(&caps [(b0 + r) * TSTEPS + t0]);
        }
    }

    for (int t = 0; t < TSTEPS; t++) {
        // x-gate gathers (issued early, consumed after the k-loop)
        float xg0 = __ldg(&tabd[(size_t)widx[0] * NGATE + c]) + __ldg(&capd[cidx[0] * NGATE + c]);
        float xg1 = __ldg(&tabd[(size_t)widx[1] * NGATE + c]) + __ldg(&capd[cidx[1] * NGATE + c]);
        float xg2 = __ldg(&tabd[(size_t)widx[2] * NGATE + c]) + __ldg(&capd[cidx[2] * NGATE + c]);
        float xg3 = __ldg(&tabd[(size_t)widx[3] * NGATE + c]) + __ldg(&capd[cidx[3] * NGATE + c]);

        // prefetch indices for next step
        if (t + 1 < TSTEPS) {
            int tt = d ? (TSTEPS - 2 - t) : (t + 1);
#pragma unroll
            for (int r = 0; r < 4; r++) {
                widx[r] = __ldg(&words[(b0 + r) * TSTEPS + tt]);
                cidx[r] = __ldg(&caps [(b0 + r) * TSTEPS + tt]);
            }
        }

        // recurrent GEMM: acc[r] = h[r] @ W_h[:, c]  (packed f32x2 over k-pairs)
        unsigned long long A0 = 0ull, A1 = 0ull, A2 = 0ull, A3 = 0ull;
        if (c < SMEM_COLS) {
#pragma unroll
            for (int k = 0; k < HID; k += 4) {
                ulonglong2 wp = *(const ulonglong2*)&wcs[k];      // LDS.128 (phase conflict-free)
                ulonglong2 h0 = *(const ulonglong2*)&h_s[0 * HID + k];  // broadcast
                ulonglong2 h1 = *(const ulonglong2*)&h_s[1 * HID + k];
                ulonglong2 h2 = *(const ulonglong2*)&h_s[2 * HID + k];
                ulonglong2 h3 = *(const ulonglong2*)&h_s[3 * HID + k];
                ffma2(A0, h0.x, wp.x); ffma2(A0, h0.y, wp.y);
                ffma2(A1, h1.x, wp.x); ffma2(A1, h1.y, wp.y);
                ffma2(A2, h2.x, wp.x); ffma2(A2, h2.y, wp.y);
                ffma2(A3, h3.x, wp.x); ffma2(A3, h3.y, wp.y);
            }
        } else {
            // tail columns: transposed weights streamed from L2 (98 KB resident)
#pragma unroll 8
            for (int k = 0; k < HID; k += 4) {
                ulonglong2 wp = *(const ulonglong2*)&wct[k];      // LDG.128, L2-hot
                ulonglong2 h0 = *(const ulonglong2*)&h_s[0 * HID + k];
                ulonglong2 h1 = *(const ulonglong2*)&h_s[1 * HID + k];
                ulonglong2 h2 = *(const ulonglong2*)&h_s[2 * HID + k];
                ulonglong2 h3 = *(const ulonglong2*)&h_s[3 * HID + k];
                ffma2(A0, h0.x, wp.x); ffma2(A0, h0.y, wp.y);
                ffma2(A1, h1.x, wp.x); ffma2(A1, h1.y, wp.y);
                ffma2(A2, h2.x, wp.x); ffma2(A2, h2.y, wp.y);
                ffma2(A3, h3.x, wp.x); ffma2(A3, h3.y, wp.y);
            }
        }
        float2 f0 = ull2f2(A0), f1 = ull2f2(A1), f2 = ull2f2(A2), f3 = ull2f2(A3);
        g_s[0 * GPITCH + c] = f0.x + f0.y + xg0;
        g_s[1 * GPITCH + c] = f1.x + f1.y + xg1;
        g_s[2 * GPITCH + c] = f2.x + f2.y + xg2;
        g_s[3 * GPITCH + c] = f3.x + f3.y + xg3;
        __syncthreads();

        // gate update: thread (r_id, u) owns one (row, hidden-unit)
        {
            float gi = g_s[r_id * GPITCH + u];
            float gj = g_s[r_id * GPITCH + u + HID];
            float gf = g_s[r_id * GPITCH + u + 2 * HID];
            float go = g_s[r_id * GPITCH + u + 3 * HID];
            cst = sigf(gf + 1.0f) * cst + sigf(gi) * tanh_fast(gj);
            hh  = sigf(go) * tanh_fast(cst);
            h_s[r_id * HID + u] = hh;
        }
        __syncthreads();
    }

    g_hfinal[((d * BATCH) + (b0 + r_id)) * HID + u] = hh;
}

// ---------------- kernel 4: dense head ----------------
__global__ void __launch_bounds__(256) dense_kernel(const float* __restrict__ W1,
                                                    const float* __restrict__ b1,
                                                    const float* __restrict__ W2,
                                                    const float* __restrict__ b2,
                                                    float* __restrict__ out)
{
    __shared__ float red[256];
    __shared__ float d1[DENSE];
    const int b = blockIdx.x, t = threadIdx.x;
    const int j = t & 63, q = t >> 6;
    // input vector x[0:256] = [h_fw_last | h_bw_first]; quarter q covers k in [q*64, q*64+64)
    const float* xin = (q < 2) ? &g_hfinal[b * HID + q * 64]
                               : &g_hfinal[(BATCH + b) * HID + (q - 2) * 64];
    const float* w   = &W1[(q * 64) * DENSE + j];
    float acc = 0.0f;
#pragma unroll 8
    for (int i = 0; i < 64; i++) acc += xin[i] * w[i * DENSE];
    red[t] = acc;
    __syncthreads();
    if (t < DENSE) {
        float a = red[t] + red[t + 64] + red[t + 128] + red[t + 192] + b1[t];
        d1[t] = (a > 0.0f) ? a : (__expf(a) - 1.0f);   // elu
    }
    __syncthreads();
    if (t < NC) {
        float a = b2[t];
#pragma unroll
        for (int k = 0; k < DENSE; k++) a += d1[k] * W2[k * NC + t];
        out[b * NC + t] = 1.0f / (1.0f + __expf(-a));  // sigmoid
    }
}

// ---------------- launch ----------------
extern "C" void kernel_launch(void* const* d_in, const int* in_sizes, int n_in,
                              void* d_out, int out_size)
{
    const int*   words = (const int*)  d_in[0];
    const int*   caps  = (const int*)  d_in[1];
    const float* emb   = (const float*)d_in[2];
    const float* cemb  = (const float*)d_in[3];
    const float* Wfw   = (const float*)d_in[4];
    const float* bfw   = (const float*)d_in[5];
    const float* Wbw   = (const float*)d_in[6];
    const float* bbw   = (const float*)d_in[7];
    const float* W1    = (const float*)d_in[8];
    const float* b1    = (const float*)d_in[9];
    const float* W2    = (const float*)d_in[10];
    const float* b2    = (const float*)d_in[11];
    float* out = (float*)d_out;

    cudaFuncSetAttribute(scan_kernel, cudaFuncAttributeMaxDynamicSharedMemorySize,
                         SCAN_SMEM_BYTES);

    wtail_kernel<<<(2 * TAILC * HID + 511) / 512, 512>>>(Wfw, Wbw);
    captab_kernel<<<8, 512>>>(cemb, Wfw, bfw, Wbw, bbw);
    tab_kernel<<<dim3((VOCABP + 15) / 16, 2), 512>>>(emb, Wfw, Wbw);
    scan_kernel<<<128, 512, SCAN_SMEM_BYTES>>>(words, caps, Wfw, Wbw);
    dense_kernel<<<BATCH, 256>>>(W1, b1, W2, b2, out);
}

// round 6
// speedup vs baseline: 1.0569x; 1.0569x over previous
#include <cuda_runtime.h>
#include <cstddef>

#define VOCABP 50001
#define EMB    200
#define HID    128
#define BATCH  256
#define TSTEPS 500
#define NC     6
#define DENSE  64
#define NGATE  512   // 4*HID
#define HOFF   203   // row offset of h-part inside W [331, 512]

#define SMEM_COLS 416                 // gate columns with fp32 weights in SMEM (13 warps)
#define TAILC     (NGATE - SMEM_COLS) // 96 columns streamed from L2 (3 warps)
#define WPITCH    132                 // smem weight pitch in floats (528B; >=HID, phase conflict-free)
#define GPITCH    512                 // gate staging pitch (read stride 128 -> distinct banks per lane)
#define SCAN_SMEM_BYTES ((SMEM_COLS*WPITCH + 4*HID + 4*GPITCH) * 4)   // 229,888 B < 232,448 cap

// ---------------- scratch (no allocations allowed) ----------------
__device__ float g_tab[2ull * VOCABP * NGATE];   // projected vocab tables, ~205 MB
__device__ float g_captab[2 * 4 * NGATE];        // cap one-hot projection + bias
__device__ float g_wtail[2 * TAILC * HID];       // transposed W_h tail cols [d][c][k]
__device__ float g_hfinal[2 * BATCH * HID];      // final hidden states per direction

__device__ __forceinline__ float sigf(float x) { return 1.0f / (1.0f + __expf(-x)); }
__device__ __forceinline__ float tanh_fast(float x) {
    return 1.0f - 2.0f / (__expf(2.0f * x) + 1.0f);
}

// packed fp32x2 FMA: d.lo += a.lo*b.lo ; d.hi += a.hi*b.hi
__device__ __forceinline__ void ffma2(unsigned long long& d,
                                      unsigned long long a, unsigned long long b) {
    asm("fma.rn.f32x2 %0, %1, %2, %0;" : "+l"(d) : "l"(a), "l"(b));
}
__device__ __forceinline__ float2 ull2f2(unsigned long long v) {
    float2 r; asm("mov.b64 {%0,%1}, %2;" : "=f"(r.x), "=f"(r.y) : "l"(v)); return r;
}
__device__ __forceinline__ unsigned long long fdup(float w) {
    unsigned long long r; asm("mov.b64 %0, {%1,%1};" : "=l"(r) : "f"(w)); return r;
}

// ---------------- kernel 1: Tab[d] = word_emb @ W_d[0:200,:] ----------------
__global__ void __launch_bounds__(512) tab_kernel(const float* __restrict__ emb,
                                                  const float* __restrict__ Wfw,
                                                  const float* __restrict__ Wbw)
{
    __shared__ float es[EMB * 16];   // [k][r] transposed tile, 12.8 KB
    const int d  = blockIdx.y;
    const int v0 = blockIdx.x * 16;
    const float* __restrict__ W = d ? Wbw : Wfw;
    const int tid = threadIdx.x;

    for (int i = tid; i < 16 * EMB; i += 512) {
        int r = i / EMB, k = i % EMB;
        int v = v0 + r;
        es[k * 16 + r] = (v < VOCABP) ? emb[(size_t)v * EMB + k] : 0.0f;
    }
    __syncthreads();

    const int c = tid;   // gate column 0..511
    unsigned long long acc[8];  // 8 packed pairs = 16 rows
#pragma unroll
    for (int p = 0; p < 8; p++) acc[p] = 0ull;

#pragma unroll 4
    for (int k = 0; k < EMB; k++) {
        unsigned long long wd = fdup(__ldg(&W[k * NGATE + c]));
        const ulonglong2* e2 = (const ulonglong2*)&es[k * 16];
        ulonglong2 ea = e2[0], eb = e2[1], ec = e2[2], ed = e2[3];
        ffma2(acc[0], ea.x, wd); ffma2(acc[1], ea.y, wd);
        ffma2(acc[2], eb.x, wd); ffma2(acc[3], eb.y, wd);
        ffma2(acc[4], ec.x, wd); ffma2(acc[5], ec.y, wd);
        ffma2(acc[6], ed.x, wd); ffma2(acc[7], ed.y, wd);
    }

    float* out = &g_tab[((size_t)d * VOCABP + v0) * NGATE + c];
#pragma unroll
    for (int p = 0; p < 8; p++) {
        float2 f = ull2f2(acc[p]);
        if (v0 + 2 * p     < VOCABP) out[(size_t)(2 * p)     * NGATE] = f.x;
        if (v0 + 2 * p + 1 < VOCABP) out[(size_t)(2 * p + 1) * NGATE] = f.y;
    }
}

// ---------------- kernel 2a: cap table (+ bias folded in) ----------------
__global__ void captab_kernel(const float* __restrict__ cemb,
                              const float* __restrict__ Wfw, const float* __restrict__ bfw,
                              const float* __restrict__ Wbw, const float* __restrict__ bbw)
{
    int idx = blockIdx.x * blockDim.x + threadIdx.x;
    if (idx >= 2 * 4 * NGATE) return;
    int d  = idx / (4 * NGATE);
    int ci = (idx / NGATE) & 3;
    int c  = idx % NGATE;
    const float* W = d ? Wbw : Wfw;
    const float* b = d ? bbw : bfw;
    float v = b[c];
#pragma unroll
    for (int j = 0; j < 3; j++) v += cemb[ci * 3 + j] * W[(EMB + j) * NGATE + c];
    g_captab[idx] = v;
}

// ---------------- kernel 2b: transpose tail W_h columns into g_wtail ----------------
__global__ void wtail_kernel(const float* __restrict__ Wfw, const float* __restrict__ Wbw)
{
    int idx = blockIdx.x * blockDim.x + threadIdx.x;
    if (idx >= 2 * TAILC * HID) return;
    int d  = idx / (TAILC * HID);
    int ct = (idx / HID) % TAILC;
    int k  = idx % HID;
    const float* W = d ? Wbw : Wfw;
    g_wtail[idx] = W[(HOFF + k) * NGATE + SMEM_COLS + ct];
}

// ---------------- kernel 3: the recurrent scan ----------------
// grid = 128 CTAs: blockIdx.x>>6 = direction, (blockIdx.x&63)*4 = first batch row
// 512 threads: thread c computes gate column c for 4 batch rows.
__global__ void __launch_bounds__(512, 1) scan_kernel(const int* __restrict__ words,
                                                      const int* __restrict__ caps,
                                                      const float* __restrict__ Wfw,
                                                      const float* __restrict__ Wbw)
{
    extern __shared__ float sm[];
    float* Ws  = sm;                        // [SMEM_COLS][WPITCH]  transposed, ~219.6 KB
    float* h_s = Ws + SMEM_COLS * WPITCH;   // [4][HID]
    float* g_s = h_s + 4 * HID;             // [4][GPITCH]

    const int tid = threadIdx.x;
    const int d   = blockIdx.x >> 6;
    const int b0  = (blockIdx.x & 63) * 4;
    const float* __restrict__ W = d ? Wbw : Wfw;

    // stage W_h columns [0, SMEM_COLS) transposed: Ws[c][k]
    for (int i = tid; i < HID * SMEM_COLS; i += 512) {
        int k = i / SMEM_COLS, c = i % SMEM_COLS;   // coalesced global read
        Ws[c * WPITCH + k] = W[(HOFF + k) * NGATE + c];
    }
    if (tid < 4 * HID) h_s[tid] = 0.0f;

    const int r_id = tid >> 7;     // gate-update mapping: row
    const int u    = tid & 127;    // hidden unit
    float cst = 0.0f;              // cell state lives in registers
    float hh  = 0.0f;

    const int c = tid;             // gate column
    const bool is_tail = (c >= SMEM_COLS);  // warp-uniform (warps 13..15)
    const float* __restrict__ tabd = &g_tab[(size_t)d * VOCABP * NGATE];
    const float* __restrict__ capd = &g_captab[d * 4 * NGATE];
    const float* __restrict__ wcs  = &Ws[c * WPITCH];   // smem weight path
    const float* __restrict__ wct  = &g_wtail[(d * TAILC + (c - SMEM_COLS)) * HID]; // L2 tail

    // cap-gate contributions preloaded (cap indices are 0..2)
    const float cap0 = __ldg(&capd[0 * NGATE + c]);
    const float cap1 = __ldg(&capd[1 * NGATE + c]);
    const float cap2 = __ldg(&capd[2 * NGATE + c]);

    __syncthreads();

    // prefetch indices for t = 0
    int widx[4], cidx[4];
    {
        int t0 = d ? (TSTEPS - 1) : 0;
#pragma unroll
        for (int r = 0; r < 4; r++) {
            widx[r] = __ldg(&words[(b0 + r) * TSTEPS + t0]);
            cidx[r] = __ldg(&caps [(b0 + r) * TSTEPS + t0]);
        }
    }

    for (int t = 0; t < TSTEPS; t++) {
        // x-gate gathers (issued early, consumed after the k-loop)
        float xg0 = __ldg(&tabd[(size_t)widx[0] * NGATE + c]);
        float xg1 = __ldg(&tabd[(size_t)widx[1] * NGATE + c]);
        float xg2 = __ldg(&tabd[(size_t)widx[2] * NGATE + c]);
        float xg3 = __ldg(&tabd[(size_t)widx[3] * NGATE + c]);
        xg0 += (cidx[0] == 0) ? cap0 : ((cidx[0] == 1) ? cap1 : cap2);
        xg1 += (cidx[1] == 0) ? cap0 : ((cidx[1] == 1) ? cap1 : cap2);
        xg2 += (cidx[2] == 0) ? cap0 : ((cidx[2] == 1) ? cap1 : cap2);
        xg3 += (cidx[3] == 0) ? cap0 : ((cidx[3] == 1) ? cap1 : cap2);

        // prefetch indices for next step
        if (t + 1 < TSTEPS) {
            int tt = d ? (TSTEPS - 2 - t) : (t + 1);
#pragma unroll
            for (int r = 0; r < 4; r++) {
                widx[r] = __ldg(&words[(b0 + r) * TSTEPS + tt]);
                cidx[r] = __ldg(&caps [(b0 + r) * TSTEPS + tt]);
            }
        }

        // recurrent GEMM: acc[r] = h[r] @ W_h[:, c]  (packed f32x2 over k-pairs)
        unsigned long long A0 = 0ull, A1 = 0ull, A2 = 0ull, A3 = 0ull;
        if (!is_tail) {
            // bounded unroll: 20 LDS.128 per batched iteration, inside LSU budget
#pragma unroll 4
            for (int k = 0; k < HID; k += 4) {
                ulonglong2 wp = *(const ulonglong2*)&wcs[k];            // LDS.128 conflict-free
                ulonglong2 h0 = *(const ulonglong2*)&h_s[0 * HID + k];  // broadcast
                ulonglong2 h1 = *(const ulonglong2*)&h_s[1 * HID + k];
                ulonglong2 h2 = *(const ulonglong2*)&h_s[2 * HID + k];
                ulonglong2 h3 = *(const ulonglong2*)&h_s[3 * HID + k];
                ffma2(A0, h0.x, wp.x); ffma2(A0, h0.y, wp.y);
                ffma2(A1, h1.x, wp.x); ffma2(A1, h1.y, wp.y);
                ffma2(A2, h2.x, wp.x); ffma2(A2, h2.y, wp.y);
                ffma2(A3, h3.x, wp.x); ffma2(A3, h3.y, wp.y);
            }
        } else {
            // tail columns: transposed fp32 weights streamed from L2 (~98 KB resident)
            // unroll 8 -> ~10 LDG.128 in flight to cover L2 latency
#pragma unroll 8
            for (int k = 0; k < HID; k += 4) {
                ulonglong2 wp = *(const ulonglong2*)&wct[k];            // LDG.128, L2-hot
                ulonglong2 h0 = *(const ulonglong2*)&h_s[0 * HID + k];
                ulonglong2 h1 = *(const ulonglong2*)&h_s[1 * HID + k];
                ulonglong2 h2 = *(const ulonglong2*)&h_s[2 * HID + k];
                ulonglong2 h3 = *(const ulonglong2*)&h_s[3 * HID + k];
                ffma2(A0, h0.x, wp.x); ffma2(A0, h0.y, wp.y);
                ffma2(A1, h1.x, wp.x); ffma2(A1, h1.y, wp.y);
                ffma2(A2, h2.x, wp.x); ffma2(A2, h2.y, wp.y);
                ffma2(A3, h3.x, wp.x); ffma2(A3, h3.y, wp.y);
            }
        }
        float2 f0 = ull2f2(A0), f1 = ull2f2(A1), f2 = ull2f2(A2), f3 = ull2f2(A3);
        g_s[0 * GPITCH + c] = f0.x + f0.y + xg0;
        g_s[1 * GPITCH + c] = f1.x + f1.y + xg1;
        g_s[2 * GPITCH + c] = f2.x + f2.y + xg2;
        g_s[3 * GPITCH + c] = f3.x + f3.y + xg3;
        __syncthreads();

        // gate update: thread (r_id, u) owns one (row, hidden-unit)
        {
            float gi = g_s[r_id * GPITCH + u];
            float gj = g_s[r_id * GPITCH + u + HID];
            float gf = g_s[r_id * GPITCH + u + 2 * HID];
            float go = g_s[r_id * GPITCH + u + 3 * HID];
            cst = sigf(gf + 1.0f) * cst + sigf(gi) * tanh_fast(gj);
            hh  = sigf(go) * tanh_fast(cst);
            h_s[r_id * HID + u] = hh;
        }
        __syncthreads();
    }

    g_hfinal[((d * BATCH) + (b0 + r_id)) * HID + u] = hh;
}

// ---------------- kernel 4: dense head ----------------
__global__ void __launch_bounds__(256) dense_kernel(const float* __restrict__ W1,
                                                    const float* __restrict__ b1,
                                                    const float* __restrict__ W2,
                                                    const float* __restrict__ b2,
                                                    float* __restrict__ out)
{
    __shared__ float red[256];
    __shared__ float d1[DENSE];
    const int b = blockIdx.x, t = threadIdx.x;
    const int j = t & 63, q = t >> 6;
    const float* xin = (q < 2) ? &g_hfinal[b * HID + q * 64]
                               : &g_hfinal[(BATCH + b) * HID + (q - 2) * 64];
    const float* w   = &W1[(q * 64) * DENSE + j];
    float acc = 0.0f;
#pragma unroll 8
    for (int i = 0; i < 64; i++) acc += xin[i] * w[i * DENSE];
    red[t] = acc;
    __syncthreads();
    if (t < DENSE) {
        float a = red[t] + red[t + 64] + red[t + 128] + red[t + 192] + b1[t];
        d1[t] = (a > 0.0f) ? a : (__expf(a) - 1.0f);   // elu
    }
    __syncthreads();
    if (t < NC) {
        float a = b2[t];
#pragma unroll
        for (int k = 0; k < DENSE; k++) a += d1[k] * W2[k * NC + t];
        out[b * NC + t] = 1.0f / (1.0f + __expf(-a));  // sigmoid
    }
}

// ---------------- launch ----------------
extern "C" void kernel_launch(void* const* d_in, const int* in_sizes, int n_in,
                              void* d_out, int out_size)
{
    const int*   words = (const int*)  d_in[0];
    const int*   caps  = (const int*)  d_in[1];
    const float* emb   = (const float*)d_in[2];
    const float* cemb  = (const float*)d_in[3];
    const float* Wfw   = (const float*)d_in[4];
    const float* bfw   = (const float*)d_in[5];
    const float* Wbw   = (const float*)d_in[6];
    const float* bbw   = (const float*)d_in[7];
    const float* W1    = (const float*)d_in[8];
    const float* b1    = (const float*)d_in[9];
    const float* W2    = (const float*)d_in[10];
    const float* b2    = (const float*)d_in[11];
    float* out = (float*)d_out;

    cudaFuncSetAttribute(scan_kernel, cudaFuncAttributeMaxDynamicSharedMemorySize,
                         SCAN_SMEM_BYTES);

    wtail_kernel<<<(2 * TAILC * HID + 511) / 512, 512>>>(Wfw, Wbw);
    captab_kernel<<<8, 512>>>(cemb, Wfw, bfw, Wbw, bbw);
    tab_kernel<<<dim3((VOCABP + 15) / 16, 2), 512>>>(emb, Wfw, Wbw);
    scan_kernel<<<128, 512, SCAN_SMEM_BYTES>>>(words, caps, Wfw, Wbw);
    dense_kernel<<<BATCH, 256>>>(W1, b1, W2, b2, out);
}

// round 7
// speedup vs baseline: 1.2617x; 1.1938x over previous
#include <cuda_runtime.h>
#include <cstddef>

#define VOCABP 50001
#define EMB    200
#define HID    128
#define BATCH  256
#define TSTEPS 500
#define NC     6
#define DENSE  64
#define NGATE  512   // 4*HID
#define HOFF   203   // row offset of h-part inside W [331, 512]

#define SCAN_T    256                 // scan threads: (4 rows x 2 cols) per thread
#define SMEM_COLS 416                 // gate columns with fp32 weights in SMEM
#define TAILC     (NGATE - SMEM_COLS) // 96 columns streamed from L2 (threads j>=160, warps 5-7)
#define GPITCH    516                 // gate staging pitch
#define SCAN_SMEM_BYTES ((HID*SMEM_COLS + 4*HID + 4*GPITCH) * 4)   // 223,296 B <= 232,448 cap

// ---------------- scratch (no allocations allowed) ----------------
__device__ float g_tab[2ull * VOCABP * NGATE];   // projected vocab tables, ~205 MB
__device__ float g_captab[2 * 4 * NGATE];        // cap one-hot projection + bias
__device__ float g_wtail[2 * HID * TAILC];       // tail W_h, k-major: [d][k][ct] for dense lane reads
__device__ float g_hfinal[2 * BATCH * HID];      // final hidden states per direction

__device__ __forceinline__ float sigf(float x) { return 1.0f / (1.0f + __expf(-x)); }
__device__ __forceinline__ float tanh_fast(float x) {
    return 1.0f - 2.0f / (__expf(2.0f * x) + 1.0f);
}

// packed fp32x2 helpers (used in tab_kernel only)
__device__ __forceinline__ void ffma2(unsigned long long& d,
                                      unsigned long long a, unsigned long long b) {
    asm("fma.rn.f32x2 %0, %1, %2, %0;" : "+l"(d) : "l"(a), "l"(b));
}
__device__ __forceinline__ float2 ull2f2(unsigned long long v) {
    float2 r; asm("mov.b64 {%0,%1}, %2;" : "=f"(r.x), "=f"(r.y) : "l"(v)); return r;
}
__device__ __forceinline__ unsigned long long fdup(float w) {
    unsigned long long r; asm("mov.b64 %0, {%1,%1};" : "=l"(r) : "f"(w)); return r;
}

// ---------------- kernel 1: Tab[d] = word_emb @ W_d[0:200,:] ----------------
__global__ void __launch_bounds__(512) tab_kernel(const float* __restrict__ emb,
                                                  const float* __restrict__ Wfw,
                                                  const float* __restrict__ Wbw)
{
    __shared__ float es[EMB * 16];   // [k][r] transposed tile, 12.8 KB
    const int d  = blockIdx.y;
    const int v0 = blockIdx.x * 16;
    const float* __restrict__ W = d ? Wbw : Wfw;
    const int tid = threadIdx.x;

    for (int i = tid; i < 16 * EMB; i += 512) {
        int r = i / EMB, k = i % EMB;
        int v = v0 + r;
        es[k * 16 + r] = (v < VOCABP) ? emb[(size_t)v * EMB + k] : 0.0f;
    }
    __syncthreads();

    const int c = tid;   // gate column 0..511
    unsigned long long acc[8];  // 8 packed pairs = 16 rows
#pragma unroll
    for (int p = 0; p < 8; p++) acc[p] = 0ull;

#pragma unroll 4
    for (int k = 0; k < EMB; k++) {
        unsigned long long wd = fdup(__ldg(&W[k * NGATE + c]));
        const ulonglong2* e2 = (const ulonglong2*)&es[k * 16];
        ulonglong2 ea = e2[0], eb = e2[1], ec = e2[2], ed = e2[3];
        ffma2(acc[0], ea.x, wd); ffma2(acc[1], ea.y, wd);
        ffma2(acc[2], eb.x, wd); ffma2(acc[3], eb.y, wd);
        ffma2(acc[4], ec.x, wd); ffma2(acc[5], ec.y, wd);
        ffma2(acc[6], ed.x, wd); ffma2(acc[7], ed.y, wd);
    }

    float* out = &g_tab[((size_t)d * VOCABP + v0) * NGATE + c];
#pragma unroll
    for (int p = 0; p < 8; p++) {
        float2 f = ull2f2(acc[p]);
        if (v0 + 2 * p     < VOCABP) out[(size_t)(2 * p)     * NGATE] = f.x;
        if (v0 + 2 * p + 1 < VOCABP) out[(size_t)(2 * p + 1) * NGATE] = f.y;
    }
}

// ---------------- kernel 2a: cap table (+ bias folded in) ----------------
__global__ void captab_kernel(const float* __restrict__ cemb,
                              const float* __restrict__ Wfw, const float* __restrict__ bfw,
                              const float* __restrict__ Wbw, const float* __restrict__ bbw)
{
    int idx = blockIdx.x * blockDim.x + threadIdx.x;
    if (idx >= 2 * 4 * NGATE) return;
    int d  = idx / (4 * NGATE);
    int ci = (idx / NGATE) & 3;
    int c  = idx % NGATE;
    const float* W = d ? Wbw : Wfw;
    const float* b = d ? bbw : bfw;
    float v = b[c];
#pragma unroll
    for (int j = 0; j < 3; j++) v += cemb[ci * 3 + j] * W[(EMB + j) * NGATE + c];
    g_captab[idx] = v;
}

// ---------------- kernel 2b: tail W_h columns, k-major: g_wtail[d][k][ct] ----------------
__global__ void wtail_kernel(const float* __restrict__ Wfw, const float* __restrict__ Wbw)
{
    int idx = blockIdx.x * blockDim.x + threadIdx.x;
    if (idx >= 2 * HID * TAILC) return;
    int d  = idx / (HID * TAILC);
    int k  = (idx / TAILC) % HID;
    int ct = idx % TAILC;
    const float* W = d ? Wbw : Wfw;
    g_wtail[idx] = W[(HOFF + k) * NGATE + SMEM_COLS + ct];
}

// ---------------- kernel 3: the recurrent scan ----------------
// grid = 128 CTAs: blockIdx.x>>6 = direction, (blockIdx.x&63)*4 = first batch row
// 256 threads: thread j computes gate columns j and j+256 for 4 batch rows.
__global__ void __launch_bounds__(SCAN_T, 1) scan_kernel(const int* __restrict__ words,
                                                         const int* __restrict__ caps,
                                                         const float* __restrict__ Wfw,
                                                         const float* __restrict__ Wbw)
{
    extern __shared__ float sm[];
    float* Ws  = sm;                       // [HID][SMEM_COLS]  non-transposed (LDS.32 dense)
    float* h_s = Ws + HID * SMEM_COLS;     // [4][HID]
    float* g_s = h_s + 4 * HID;            // [4][GPITCH]

    const int tid = threadIdx.x;           // j = first column
    const int d   = blockIdx.x >> 6;
    const int b0  = (blockIdx.x & 63) * 4;
    const float* __restrict__ W = d ? Wbw : Wfw;

    // stage W_h columns [0, SMEM_COLS) into SMEM, row-major
    for (int i = tid; i < HID * SMEM_COLS; i += SCAN_T) {
        int k = i / SMEM_COLS, c = i % SMEM_COLS;
        Ws[i] = W[(HOFF + k) * NGATE + c];
    }
    for (int i = tid; i < 4 * HID; i += SCAN_T) h_s[i] = 0.0f;

    const int c0 = tid;            // first column  (< 256, always in SMEM)
    const int c1 = tid + 256;      // second column (tail if >= SMEM_COLS, i.e. tid >= 160)
    const bool is_tail = (c1 >= SMEM_COLS);   // warp-uniform: warps 5,6,7
    const float* __restrict__ tabd = &g_tab[(size_t)d * VOCABP * NGATE];
    const float* __restrict__ capd = &g_captab[d * 4 * NGATE];
    const float* __restrict__ wt2  = &g_wtail[d * HID * TAILC + (c1 - SMEM_COLS)]; // [k][ct]

    // cap-gate contributions preloaded (cap indices 0..2) for both columns
    const float capA0 = __ldg(&capd[0 * NGATE + c0]);
    const float capA1 = __ldg(&capd[1 * NGATE + c0]);
    const float capA2 = __ldg(&capd[2 * NGATE + c0]);
    const float capB0 = __ldg(&capd[0 * NGATE + c1]);
    const float capB1 = __ldg(&capd[1 * NGATE + c1]);
    const float capB2 = __ldg(&capd[2 * NGATE + c1]);

    // gate-update mapping: thread j updates rows {row0,row0+1}, unit u
    const int row0 = (tid >> 7) * 2;
    const int u    = tid & 127;
    float cst0 = 0.0f, cst1 = 0.0f, hh0 = 0.0f, hh1 = 0.0f;

    __syncthreads();

    // prefetch indices for t = 0
    int widx[4], cidx[4];
    {
        int t0 = d ? (TSTEPS - 1) : 0;
#pragma unroll
        for (int r = 0; r < 4; r++) {
            widx[r] = __ldg(&words[(b0 + r) * TSTEPS + t0]);
            cidx[r] = __ldg(&caps [(b0 + r) * TSTEPS + t0]);
        }
    }

    for (int t = 0; t < TSTEPS; t++) {
        // x-gate gathers for both columns (issued early)
        float xa0 = __ldg(&tabd[(size_t)widx[0] * NGATE + c0]);
        float xa1 = __ldg(&tabd[(size_t)widx[1] * NGATE + c0]);
        float xa2 = __ldg(&tabd[(size_t)widx[2] * NGATE + c0]);
        float xa3 = __ldg(&tabd[(size_t)widx[3] * NGATE + c0]);
        float xb0 = __ldg(&tabd[(size_t)widx[0] * NGATE + c1]);
        float xb1 = __ldg(&tabd[(size_t)widx[1] * NGATE + c1]);
        float xb2 = __ldg(&tabd[(size_t)widx[2] * NGATE + c1]);
        float xb3 = __ldg(&tabd[(size_t)widx[3] * NGATE + c1]);
        xa0 += (cidx[0] == 0) ? capA0 : ((cidx[0] == 1) ? capA1 : capA2);
        xa1 += (cidx[1] == 0) ? capA0 : ((cidx[1] == 1) ? capA1 : capA2);
        xa2 += (cidx[2] == 0) ? capA0 : ((cidx[2] == 1) ? capA1 : capA2);
        xa3 += (cidx[3] == 0) ? capA0 : ((cidx[3] == 1) ? capA1 : capA2);
        xb0 += (cidx[0] == 0) ? capB0 : ((cidx[0] == 1) ? capB1 : capB2);
        xb1 += (cidx[1] == 0) ? capB0 : ((cidx[1] == 1) ? capB1 : capB2);
        xb2 += (cidx[2] == 0) ? capB0 : ((cidx[2] == 1) ? capB1 : capB2);
        xb3 += (cidx[3] == 0) ? capB0 : ((cidx[3] == 1) ? capB1 : capB2);

        // prefetch indices for next step
        if (t + 1 < TSTEPS) {
            int tt = d ? (TSTEPS - 2 - t) : (t + 1);
#pragma unroll
            for (int r = 0; r < 4; r++) {
                widx[r] = __ldg(&words[(b0 + r) * TSTEPS + tt]);
                cidx[r] = __ldg(&caps [(b0 + r) * TSTEPS + tt]);
            }
        }

        // recurrent GEMM: 2 columns x 4 rows per thread, scalar FFMA
        float a0 = 0.f, a1 = 0.f, a2 = 0.f, a3 = 0.f;   // col c0
        float e0 = 0.f, e1 = 0.f, e2 = 0.f, e3 = 0.f;   // col c1
        if (!is_tail) {
#pragma unroll 4
            for (int k = 0; k < HID; k += 4) {
                float4 h0 = *(const float4*)&h_s[0 * HID + k];   // broadcast
                float4 h1 = *(const float4*)&h_s[1 * HID + k];
                float4 h2 = *(const float4*)&h_s[2 * HID + k];
                float4 h3 = *(const float4*)&h_s[3 * HID + k];
                float wa0 = Ws[(k + 0) * SMEM_COLS + c0];        // dense LDS.32
                float wa1 = Ws[(k + 1) * SMEM_COLS + c0];
                float wa2 = Ws[(k + 2) * SMEM_COLS + c0];
                float wa3 = Ws[(k + 3) * SMEM_COLS + c0];
                float wb0 = Ws[(k + 0) * SMEM_COLS + c1];
                float wb1 = Ws[(k + 1) * SMEM_COLS + c1];
                float wb2 = Ws[(k + 2) * SMEM_COLS + c1];
                float wb3 = Ws[(k + 3) * SMEM_COLS + c1];
                a0 += h0.x*wa0 + h0.y*wa1 + h0.z*wa2 + h0.w*wa3;
                a1 += h1.x*wa0 + h1.y*wa1 + h1.z*wa2 + h1.w*wa3;
                a2 += h2.x*wa0 + h2.y*wa1 + h2.z*wa2 + h2.w*wa3;
                a3 += h3.x*wa0 + h3.y*wa1 + h3.z*wa2 + h3.w*wa3;
                e0 += h0.x*wb0 + h0.y*wb1 + h0.z*wb2 + h0.w*wb3;
                e1 += h1.x*wb0 + h1.y*wb1 + h1.z*wb2 + h1.w*wb3;
                e2 += h2.x*wb0 + h2.y*wb1 + h2.z*wb2 + h2.w*wb3;
                e3 += h3.x*wb0 + h3.y*wb1 + h3.z*wb2 + h3.w*wb3;
            }
        } else {
            // second column streamed from L2, k-major layout -> dense lane reads
#pragma unroll 4
            for (int k = 0; k < HID; k += 4) {
                float4 h0 = *(const float4*)&h_s[0 * HID + k];
                float4 h1 = *(const float4*)&h_s[1 * HID + k];
                float4 h2 = *(const float4*)&h_s[2 * HID + k];
                float4 h3 = *(const float4*)&h_s[3 * HID + k];
                float wa0 = Ws[(k + 0) * SMEM_COLS + c0];
                float wa1 = Ws[(k + 1) * SMEM_COLS + c0];
                float wa2 = Ws[(k + 2) * SMEM_COLS + c0];
                float wa3 = Ws[(k + 3) * SMEM_COLS + c0];
                float wb0 = __ldg(&wt2[(k + 0) * TAILC]);        // dense LDG.32, L2-hot
                float wb1 = __ldg(&wt2[(k + 1) * TAILC]);
                float wb2 = __ldg(&wt2[(k + 2) * TAILC]);
                float wb3 = __ldg(&wt2[(k + 3) * TAILC]);
                a0 += h0.x*wa0 + h0.y*wa1 + h0.z*wa2 + h0.w*wa3;
                a1 += h1.x*wa0 + h1.y*wa1 + h1.z*wa2 + h1.w*wa3;
                a2 += h2.x*wa0 + h2.y*wa1 + h2.z*wa2 + h2.w*wa3;
                a3 += h3.x*wa0 + h3.y*wa1 + h3.z*wa2 + h3.w*wa3;
                e0 += h0.x*wb0 + h0.y*wb1 + h0.z*wb2 + h0.w*wb3;
                e1 += h1.x*wb0 + h1.y*wb1 + h1.z*wb2 + h1.w*wb3;
                e2 += h2.x*wb0 + h2.y*wb1 + h2.z*wb2 + h2.w*wb3;
                e3 += h3.x*wb0 + h3.y*wb1 + h3.z*wb2 + h3.w*wb3;
            }
        }
        g_s[0 * GPITCH + c0] = a0 + xa0;
        g_s[1 * GPITCH + c0] = a1 + xa1;
        g_s[2 * GPITCH + c0] = a2 + xa2;
        g_s[3 * GPITCH + c0] = a3 + xa3;
        g_s[0 * GPITCH + c1] = e0 + xb0;
        g_s[1 * GPITCH + c1] = e1 + xb1;
        g_s[2 * GPITCH + c1] = e2 + xb2;
        g_s[3 * GPITCH + c1] = e3 + xb3;
        __syncthreads();

        // gate update: thread j owns (rows row0, row0+1) x unit u
        {
            float gi0 = g_s[(row0 + 0) * GPITCH + u];
            float gj0 = g_s[(row0 + 0) * GPITCH + u + HID];
            float gf0 = g_s[(row0 + 0) * GPITCH + u + 2 * HID];
            float go0 = g_s[(row0 + 0) * GPITCH + u + 3 * HID];
            float gi1 = g_s[(row0 + 1) * GPITCH + u];
            float gj1 = g_s[(row0 + 1) * GPITCH + u + HID];
            float gf1 = g_s[(row0 + 1) * GPITCH + u + 2 * HID];
            float go1 = g_s[(row0 + 1) * GPITCH + u + 3 * HID];
            cst0 = sigf(gf0 + 1.0f) * cst0 + sigf(gi0) * tanh_fast(gj0);
            cst1 = sigf(gf1 + 1.0f) * cst1 + sigf(gi1) * tanh_fast(gj1);
            hh0  = sigf(go0) * tanh_fast(cst0);
            hh1  = sigf(go1) * tanh_fast(cst1);
            h_s[(row0 + 0) * HID + u] = hh0;
            h_s[(row0 + 1) * HID + u] = hh1;
        }
        __syncthreads();
    }

    g_hfinal[((d * BATCH) + (b0 + row0 + 0)) * HID + u] = hh0;
    g_hfinal[((d * BATCH) + (b0 + row0 + 1)) * HID + u] = hh1;
}

// ---------------- kernel 4: dense head ----------------
__global__ void __launch_bounds__(256) dense_kernel(const float* __restrict__ W1,
                                                    const float* __restrict__ b1,
                                                    const float* __restrict__ W2,
                                                    const float* __restrict__ b2,
                                                    float* __restrict__ out)
{
    __shared__ float red[256];
    __shared__ float d1[DENSE];
    const int b = blockIdx.x, t = threadIdx.x;
    const int j = t & 63, q = t >> 6;
    const float* xin = (q < 2) ? &g_hfinal[b * HID + q * 64]
                               : &g_hfinal[(BATCH + b) * HID + (q - 2) * 64];
    const float* w   = &W1[(q * 64) * DENSE + j];
    float acc = 0.0f;
#pragma unroll 8
    for (int i = 0; i < 64; i++) acc += xin[i] * w[i * DENSE];
    red[t] = acc;
    __syncthreads();
    if (t < DENSE) {
        float a = red[t] + red[t + 64] + red[t + 128] + red[t + 192] + b1[t];
        d1[t] = (a > 0.0f) ? a : (__expf(a) - 1.0f);   // elu
    }
    __syncthreads();
    if (t < NC) {
        float a = b2[t];
#pragma unroll
        for (int k = 0; k < DENSE; k++) a += d1[k] * W2[k * NC + t];
        out[b * NC + t] = 1.0f / (1.0f + __expf(-a));  // sigmoid
    }
}

// ---------------- launch ----------------
extern "C" void kernel_launch(void* const* d_in, const int* in_sizes, int n_in,
                              void* d_out, int out_size)
{
    const int*   words = (const int*)  d_in[0];
    const int*   caps  = (const int*)  d_in[1];
    const float* emb   = (const float*)d_in[2];
    const float* cemb  = (const float*)d_in[3];
    const float* Wfw   = (const float*)d_in[4];
    const float* bfw   = (const float*)d_in[5];
    const float* Wbw   = (const float*)d_in[6];
    const float* bbw   = (const float*)d_in[7];
    const float* W1    = (const float*)d_in[8];
    const float* b1    = (const float*)d_in[9];
    const float* W2    = (const float*)d_in[10];
    const float* b2    = (const float*)d_in[11];
    float* out = (float*)d_out;

    cudaFuncSetAttribute(scan_kernel, cudaFuncAttributeMaxDynamicSharedMemorySize,
                         SCAN_SMEM_BYTES);

    wtail_kernel<<<(2 * HID * TAILC + 511) / 512, 512>>>(Wfw, Wbw);
    captab_kernel<<<8, 512>>>(cemb, Wfw, bfw, Wbw, bbw);
    tab_kernel<<<dim3((VOCABP + 15) / 16, 2), 512>>>(emb, Wfw, Wbw);
    scan_kernel<<<128, SCAN_T, SCAN_SMEM_BYTES>>>(words, caps, Wfw, Wbw);
    dense_kernel<<<BATCH, 256>>>(W1, b1, W2, b2, out);
}

// round 8
// speedup vs baseline: 1.3577x; 1.0761x over previous
#include <cuda_runtime.h>
#include <cstddef>

#define VOCABP 50001
#define EMB    200
#define HID    128
#define BATCH  256
#define TSTEPS 500
#define NC     6
#define DENSE  64
#define NGATE  512   // 4*HID
#define HOFF   203   // row offset of h-part inside W [331, 512]

#define SCAN_T    256                 // scan threads: (4 rows x 2 cols) per thread
#define SMEM_COLS 416                 // gate columns with fp32 weights in SMEM (transposed)
#define TAILC     (NGATE - SMEM_COLS) // 96 columns streamed from L2 (threads 160..255)
#define WPITCH    132                 // transposed weight pitch in floats (528B = 33*16B)
#define GPITCH    516                 // gate staging pitch
// Ws(416*132) + h(4*128) + g(4*516) floats = 229,952 B <= 232,448 opt-in cap
#define SCAN_SMEM_BYTES ((SMEM_COLS*WPITCH + 4*HID + 4*GPITCH) * 4)

// ---------------- scratch (no allocations allowed) ----------------
__device__ float g_tab[2ull * VOCABP * NGATE];   // projected vocab tables, ~205 MB
__device__ float g_captab[2 * 4 * NGATE];        // cap one-hot projection + bias
__device__ float g_wtail[2 * (HID/2) * TAILC * 2]; // tail W_h pair-major: [d][k/2][ct]{k,k+1}
__device__ float g_hfinal[2 * BATCH * HID];      // final hidden states per direction

__device__ __forceinline__ float sigf(float x) { return 1.0f / (1.0f + __expf(-x)); }
__device__ __forceinline__ float tanh_fast(float x) {
    return 1.0f - 2.0f / (__expf(2.0f * x) + 1.0f);
}

// packed fp32x2 FMA: d.lo += a.lo*b.lo ; d.hi += a.hi*b.hi   (exact fp32 per lane)
__device__ __forceinline__ void ffma2(unsigned long long& d,
                                      unsigned long long a, unsigned long long b) {
    asm("fma.rn.f32x2 %0, %1, %2, %0;" : "+l"(d) : "l"(a), "l"(b));
}
__device__ __forceinline__ float2 ull2f2(unsigned long long v) {
    float2 r; asm("mov.b64 {%0,%1}, %2;" : "=f"(r.x), "=f"(r.y) : "l"(v)); return r;
}
__device__ __forceinline__ unsigned long long fdup(float w) {
    unsigned long long r; asm("mov.b64 %0, {%1,%1};" : "=l"(r) : "f"(w)); return r;
}
__device__ __forceinline__ unsigned long long f2_to_ull(float2 v) {
    unsigned long long r; asm("mov.b64 %0, {%1,%2};" : "=l"(r) : "f"(v.x), "f"(v.y)); return r;
}

// ---------------- kernel 1: Tab[d] = word_emb @ W_d[0:200,:] ----------------
__global__ void __launch_bounds__(512) tab_kernel(const float* __restrict__ emb,
                                                  const float* __restrict__ Wfw,
                                                  const float* __restrict__ Wbw)
{
    __shared__ float es[EMB * 16];   // [k][r] transposed tile, 12.8 KB
    const int d  = blockIdx.y;
    const int v0 = blockIdx.x * 16;
    const float* __restrict__ W = d ? Wbw : Wfw;
    const int tid = threadIdx.x;

    for (int i = tid; i < 16 * EMB; i += 512) {
        int r = i / EMB, k = i % EMB;
        int v = v0 + r;
        es[k * 16 + r] = (v < VOCABP) ? emb[(size_t)v * EMB + k] : 0.0f;
    }
    __syncthreads();

    const int c = tid;   // gate column 0..511
    unsigned long long acc[8];  // 8 packed pairs = 16 rows
#pragma unroll
    for (int p = 0; p < 8; p++) acc[p] = 0ull;

#pragma unroll 4
    for (int k = 0; k < EMB; k++) {
        unsigned long long wd = fdup(__ldg(&W[k * NGATE + c]));
        const ulonglong2* e2 = (const ulonglong2*)&es[k * 16];
        ulonglong2 ea = e2[0], eb = e2[1], ec = e2[2], ed = e2[3];
        ffma2(acc[0], ea.x, wd); ffma2(acc[1], ea.y, wd);
        ffma2(acc[2], eb.x, wd); ffma2(acc[3], eb.y, wd);
        ffma2(acc[4], ec.x, wd); ffma2(acc[5], ec.y, wd);
        ffma2(acc[6], ed.x, wd); ffma2(acc[7], ed.y, wd);
    }

    float* out = &g_tab[((size_t)d * VOCABP + v0) * NGATE + c];
#pragma unroll
    for (int p = 0; p < 8; p++) {
        float2 f = ull2f2(acc[p]);
        if (v0 + 2 * p     < VOCABP) out[(size_t)(2 * p)     * NGATE] = f.x;
        if (v0 + 2 * p + 1 < VOCABP) out[(size_t)(2 * p + 1) * NGATE] = f.y;
    }
}

// ---------------- kernel 2a: cap table (+ bias folded in) ----------------
__global__ void captab_kernel(const float* __restrict__ cemb,
                              const float* __restrict__ Wfw, const float* __restrict__ bfw,
                              const float* __restrict__ Wbw, const float* __restrict__ bbw)
{
    int idx = blockIdx.x * blockDim.x + threadIdx.x;
    if (idx >= 2 * 4 * NGATE) return;
    int d  = idx / (4 * NGATE);
    int ci = (idx / NGATE) & 3;
    int c  = idx % NGATE;
    const float* W = d ? Wbw : Wfw;
    const float* b = d ? bbw : bfw;
    float v = b[c];
#pragma unroll
    for (int j = 0; j < 3; j++) v += cemb[ci * 3 + j] * W[(EMB + j) * NGATE + c];
    g_captab[idx] = v;
}

// ---------------- kernel 2b: tail W_h, pair-major: g_wtail[d][k/2][ct] = {W[k], W[k+1]} ----------------
__global__ void wtail_kernel(const float* __restrict__ Wfw, const float* __restrict__ Wbw)
{
    int idx = blockIdx.x * blockDim.x + threadIdx.x;   // over float2 elements
    if (idx >= 2 * (HID / 2) * TAILC) return;
    int d  = idx / ((HID / 2) * TAILC);
    int k2 = (idx / TAILC) % (HID / 2);
    int ct = idx % TAILC;
    const float* W = d ? Wbw : Wfw;
    g_wtail[idx * 2 + 0] = W[(HOFF + 2 * k2 + 0) * NGATE + SMEM_COLS + ct];
    g_wtail[idx * 2 + 1] = W[(HOFF + 2 * k2 + 1) * NGATE + SMEM_COLS + ct];
}

// ---------------- kernel 3: the recurrent scan ----------------
// grid = 128 CTAs: blockIdx.x>>6 = direction, (blockIdx.x&63)*4 = first batch row
// 256 threads: thread j computes gate columns j and j+256 for 4 batch rows (f32x2 k-pairs).
__global__ void __launch_bounds__(SCAN_T, 1) scan_kernel(const int* __restrict__ words,
                                                         const int* __restrict__ caps,
                                                         const float* __restrict__ Wfw,
                                                         const float* __restrict__ Wbw)
{
    extern __shared__ float sm[];
    float* Ws  = sm;                        // [SMEM_COLS][WPITCH] transposed weights
    float* h_s = Ws + SMEM_COLS * WPITCH;   // [4][HID]
    float* g_s = h_s + 4 * HID;             // [4][GPITCH]

    const int tid = threadIdx.x;
    const int d   = blockIdx.x >> 6;
    const int b0  = (blockIdx.x & 63) * 4;
    const float* __restrict__ W = d ? Wbw : Wfw;

    // stage W_h columns [0, SMEM_COLS) transposed: Ws[c][k]  (one-time cost)
    for (int i = tid; i < HID * SMEM_COLS; i += SCAN_T) {
        int k = i / SMEM_COLS, c = i % SMEM_COLS;   // coalesced global read
        Ws[c * WPITCH + k] = W[(HOFF + k) * NGATE + c];
    }
    for (int i = tid; i < 4 * HID; i += SCAN_T) h_s[i] = 0.0f;

    const int c0 = tid;            // first column  (< 256, always in SMEM)
    const int c1 = tid + 256;      // second column (tail if >= SMEM_COLS, i.e. tid >= 160)
    const bool is_tail = (c1 >= SMEM_COLS);   // warp-uniform: warps 5,6,7
    const float* __restrict__ tabd = &g_tab[(size_t)d * VOCABP * NGATE];
    const float* __restrict__ capd = &g_captab[d * 4 * NGATE];
    const float* __restrict__ wc0 = &Ws[c0 * WPITCH];
    const float* __restrict__ wc1 = &Ws[(is_tail ? 0 : c1) * WPITCH];  // dummy for tail warps
    const float2* __restrict__ wt2 = (const float2*)g_wtail
                                     + d * (HID / 2) * TAILC + (c1 - SMEM_COLS);

    // cap-gate contributions preloaded (cap indices 0..2) for both columns
    const float capA0 = __ldg(&capd[0 * NGATE + c0]);
    const float capA1 = __ldg(&capd[1 * NGATE + c0]);
    const float capA2 = __ldg(&capd[2 * NGATE + c0]);
    const float capB0 = __ldg(&capd[0 * NGATE + c1]);
    const float capB1 = __ldg(&capd[1 * NGATE + c1]);
    const float capB2 = __ldg(&capd[2 * NGATE + c1]);

    // gate-update mapping: thread j updates rows {row0,row0+1}, unit u
    const int row0 = (tid >> 7) * 2;
    const int u    = tid & 127;
    float cst0 = 0.0f, cst1 = 0.0f, hh0 = 0.0f, hh1 = 0.0f;

    __syncthreads();

    // prefetch indices for t = 0
    int widx[4], cidx[4];
    {
        int t0 = d ? (TSTEPS - 1) : 0;
#pragma unroll
        for (int r = 0; r < 4; r++) {
            widx[r] = __ldg(&words[(b0 + r) * TSTEPS + t0]);
            cidx[r] = __ldg(&caps [(b0 + r) * TSTEPS + t0]);
        }
    }

    for (int t = 0; t < TSTEPS; t++) {
        // x-gate gathers for both columns (issued early)
        float xa0 = __ldg(&tabd[(size_t)widx[0] * NGATE + c0]);
        float xa1 = __ldg(&tabd[(size_t)widx[1] * NGATE + c0]);
        float xa2 = __ldg(&tabd[(size_t)widx[2] * NGATE + c0]);
        float xa3 = __ldg(&tabd[(size_t)widx[3] * NGATE + c0]);
        float xb0 = __ldg(&tabd[(size_t)widx[0] * NGATE + c1]);
        float xb1 = __ldg(&tabd[(size_t)widx[1] * NGATE + c1]);
        float xb2 = __ldg(&tabd[(size_t)widx[2] * NGATE + c1]);
        float xb3 = __ldg(&tabd[(size_t)widx[3] * NGATE + c1]);
        xa0 += (cidx[0] == 0) ? capA0 : ((cidx[0] == 1) ? capA1 : capA2);
        xa1 += (cidx[1] == 0) ? capA0 : ((cidx[1] == 1) ? capA1 : capA2);
        xa2 += (cidx[2] == 0) ? capA0 : ((cidx[2] == 1) ? capA1 : capA2);
        xa3 += (cidx[3] == 0) ? capA0 : ((cidx[3] == 1) ? capA1 : capA2);
        xb0 += (cidx[0] == 0) ? capB0 : ((cidx[0] == 1) ? capB1 : capB2);
        xb1 += (cidx[1] == 0) ? capB0 : ((cidx[1] == 1) ? capB1 : capB2);
        xb2 += (cidx[2] == 0) ? capB0 : ((cidx[2] == 1) ? capB1 : capB2);
        xb3 += (cidx[3] == 0) ? capB0 : ((cidx[3] == 1) ? capB1 : capB2);

        // prefetch indices for next step
        if (t + 1 < TSTEPS) {
            int tt = d ? (TSTEPS - 2 - t) : (t + 1);
#pragma unroll
            for (int r = 0; r < 4; r++) {
                widx[r] = __ldg(&words[(b0 + r) * TSTEPS + tt]);
                cidx[r] = __ldg(&caps [(b0 + r) * TSTEPS + tt]);
            }
        }

        // recurrent GEMM: 2 cols x 4 rows per thread, f32x2 over k-pairs
        unsigned long long A0 = 0ull, A1 = 0ull, A2 = 0ull, A3 = 0ull;   // col c0
        unsigned long long E0 = 0ull, E1 = 0ull, E2 = 0ull, E3 = 0ull;   // col c1
        if (!is_tail) {
#pragma unroll 4
            for (int k = 0; k < HID; k += 4) {
                ulonglong2 w0 = *(const ulonglong2*)&wc0[k];   // LDS.128: pairs (k,k+1),(k+2,k+3)
                ulonglong2 w1 = *(const ulonglong2*)&wc1[k];
                ulonglong2 h0 = *(const ulonglong2*)&h_s[0 * HID + k];   // broadcast
                ulonglong2 h1 = *(const ulonglong2*)&h_s[1 * HID + k];
                ulonglong2 h2 = *(const ulonglong2*)&h_s[2 * HID + k];
                ulonglong2 h3 = *(const ulonglong2*)&h_s[3 * HID + k];
                ffma2(A0, h0.x, w0.x); ffma2(A0, h0.y, w0.y);
                ffma2(A1, h1.x, w0.x); ffma2(A1, h1.y, w0.y);
                ffma2(A2, h2.x, w0.x); ffma2(A2, h2.y, w0.y);
                ffma2(A3, h3.x, w0.x); ffma2(A3, h3.y, w0.y);
                ffma2(E0, h0.x, w1.x); ffma2(E0, h0.y, w1.y);
                ffma2(E1, h1.x, w1.x); ffma2(E1, h1.y, w1.y);
                ffma2(E2, h2.x, w1.x); ffma2(E2, h2.y, w1.y);
                ffma2(E3, h3.x, w1.x); ffma2(E3, h3.y, w1.y);
            }
        } else {
            // col c1 streamed from L2: pair-major float2 -> dense LDG.64 per lane
#pragma unroll 4
            for (int k = 0; k < HID; k += 4) {
                ulonglong2 w0 = *(const ulonglong2*)&wc0[k];
                float2 t0 = __ldg(&wt2[(k >> 1) * TAILC]);
                float2 t1 = __ldg(&wt2[((k >> 1) + 1) * TAILC]);
                unsigned long long w1x = f2_to_ull(t0);
                unsigned long long w1y = f2_to_ull(t1);
                ulonglong2 h0 = *(const ulonglong2*)&h_s[0 * HID + k];
                ulonglong2 h1 = *(const ulonglong2*)&h_s[1 * HID + k];
                ulonglong2 h2 = *(const ulonglong2*)&h_s[2 * HID + k];
                ulonglong2 h3 = *(const ulonglong2*)&h_s[3 * HID + k];
                ffma2(A0, h0.x, w0.x); ffma2(A0, h0.y, w0.y);
                ffma2(A1, h1.x, w0.x); ffma2(A1, h1.y, w0.y);
                ffma2(A2, h2.x, w0.x); ffma2(A2, h2.y, w0.y);
                ffma2(A3, h3.x, w0.x); ffma2(A3, h3.y, w0.y);
                ffma2(E0, h0.x, w1x); ffma2(E0, h0.y, w1y);
                ffma2(E1, h1.x, w1x); ffma2(E1, h1.y, w1y);
                ffma2(E2, h2.x, w1x); ffma2(E2, h2.y, w1y);
                ffma2(E3, h3.x, w1x); ffma2(E3, h3.y, w1y);
            }
        }
        {
            float2 f;
            f = ull2f2(A0); g_s[0 * GPITCH + c0] = f.x + f.y + xa0;
            f = ull2f2(A1); g_s[1 * GPITCH + c0] = f.x + f.y + xa1;
            f = ull2f2(A2); g_s[2 * GPITCH + c0] = f.x + f.y + xa2;
            f = ull2f2(A3); g_s[3 * GPITCH + c0] = f.x + f.y + xa3;
            f = ull2f2(E0); g_s[0 * GPITCH + c1] = f.x + f.y + xb0;
            f = ull2f2(E1); g_s[1 * GPITCH + c1] = f.x + f.y + xb1;
            f = ull2f2(E2); g_s[2 * GPITCH + c1] = f.x + f.y + xb2;
            f = ull2f2(E3); g_s[3 * GPITCH + c1] = f.x + f.y + xb3;
        }
        __syncthreads();

        // gate update: thread j owns (rows row0, row0+1) x unit u
        {
            float gi0 = g_s[(row0 + 0) * GPITCH + u];
            float gj0 = g_s[(row0 + 0) * GPITCH + u + HID];
            float gf0 = g_s[(row0 + 0) * GPITCH + u + 2 * HID];
            float go0 = g_s[(row0 + 0) * GPITCH + u + 3 * HID];
            float gi1 = g_s[(row0 + 1) * GPITCH + u];
            float gj1 = g_s[(row0 + 1) * GPITCH + u + HID];
            float gf1 = g_s[(row0 + 1) * GPITCH + u + 2 * HID];
            float go1 = g_s[(row0 + 1) * GPITCH + u + 3 * HID];
            cst0 = sigf(gf0 + 1.0f) * cst0 + sigf(gi0) * tanh_fast(gj0);
            cst1 = sigf(gf1 + 1.0f) * cst1 + sigf(gi1) * tanh_fast(gj1);
            hh0  = sigf(go0) * tanh_fast(cst0);
            hh1  = sigf(go1) * tanh_fast(cst1);
            h_s[(row0 + 0) * HID + u] = hh0;
            h_s[(row0 + 1) * HID + u] = hh1;
        }
        __syncthreads();
    }

    g_hfinal[((d * BATCH) + (b0 + row0 + 0)) * HID + u] = hh0;
    g_hfinal[((d * BATCH) + (b0 + row0 + 1)) * HID + u] = hh1;
}

// ---------------- kernel 4: dense head ----------------
__global__ void __launch_bounds__(256) dense_kernel(const float* __restrict__ W1,
                                                    const float* __restrict__ b1,
                                                    const float* __restrict__ W2,
                                                    const float* __restrict__ b2,
                                                    float* __restrict__ out)
{
    __shared__ float red[256];
    __shared__ float d1[DENSE];
    const int b = blockIdx.x, t = threadIdx.x;
    const int j = t & 63, q = t >> 6;
    const float* xin = (q < 2) ? &g_hfinal[b * HID + q * 64]
                               : &g_hfinal[(BATCH + b) * HID + (q - 2) * 64];
    const float* w   = &W1[(q * 64) * DENSE + j];
    float acc = 0.0f;
#pragma unroll 8
    for (int i = 0; i < 64; i++) acc += xin[i] * w[i * DENSE];
    red[t] = acc;
    __syncthreads();
    if (t < DENSE) {
        float a = red[t] + red[t + 64] + red[t + 128] + red[t + 192] + b1[t];
        d1[t] = (a > 0.0f) ? a : (__expf(a) - 1.0f);   // elu
    }
    __syncthreads();
    if (t < NC) {
        float a = b2[t];
#pragma unroll
        for (int k = 0; k < DENSE; k++) a += d1[k] * W2[k * NC + t];
        out[b * NC + t] = 1.0f / (1.0f + __expf(-a));  // sigmoid
    }
}

// ---------------- launch ----------------
extern "C" void kernel_launch(void* const* d_in, const int* in_sizes, int n_in,
                              void* d_out, int out_size)
{
    const int*   words = (const int*)  d_in[0];
    const int*   caps  = (const int*)  d_in[1];
    const float* emb   = (const float*)d_in[2];
    const float* cemb  = (const float*)d_in[3];
    const float* Wfw   = (const float*)d_in[4];
    const float* bfw   = (const float*)d_in[5];
    const float* Wbw   = (const float*)d_in[6];
    const float* bbw   = (const float*)d_in[7];
    const float* W1    = (const float*)d_in[8];
    const float* b1    = (const float*)d_in[9];
    const float* W2    = (const float*)d_in[10];
    const float* b2    = (const float*)d_in[11];
    float* out = (float*)d_out;

    cudaFuncSetAttribute(scan_kernel, cudaFuncAttributeMaxDynamicSharedMemorySize,
                         SCAN_SMEM_BYTES);

    wtail_kernel<<<(2 * (HID / 2) * TAILC + 511) / 512, 512>>>(Wfw, Wbw);
    captab_kernel<<<8, 512>>>(cemb, Wfw, bfw, Wbw, bbw);
    tab_kernel<<<dim3((VOCABP + 15) / 16, 2), 512>>>(emb, Wfw, Wbw);
    scan_kernel<<<128, SCAN_T, SCAN_SMEM_BYTES>>>(words, caps, Wfw, Wbw);
    dense_kernel<<<BATCH, 256>>>(W1, b1, W2, b2, out);
}

// round 10
// speedup vs baseline: 1.4301x; 1.0533x over previous
#include <cuda_runtime.h>
#include <cstddef>

#define VOCABP 50001
#define EMB    200
#define HID    128
#define BATCH  256
#define TSTEPS 500
#define NC     6
#define DENSE  64
#define NGATE  512   // 4*HID
#define HOFF   203   // row offset of h-part inside W [331, 512]

#define SCAN_T    512                 // scan threads: (4 rows x 2 cols x half-k) per thread
#define SMEM_COLS 384                 // gate columns with fp32 weights in SMEM (transposed)
#define TAILC     (NGATE - SMEM_COLS) // 128 columns streamed from L2 (j >= 128)
#define WPITCH    132                 // transposed weight pitch in floats (528B; bank stride 4)
#define GPITCH    512                 // gate staging pitch
// Ws(384*132) + h(4*128) + g(2*4*512) floats = 221,184 B <= 232,448 opt-in cap
#define SCAN_SMEM_BYTES ((SMEM_COLS*WPITCH + 4*HID + 2*4*GPITCH) * 4)

// ---------------- scratch (no allocations allowed) ----------------
__device__ float g_tab[2ull * VOCABP * NGATE];    // projected vocab tables, ~205 MB
__device__ float g_captab[2 * 4 * NGATE];         // cap one-hot projection + bias
__device__ float g_wtail[2 * (HID/2) * TAILC * 2];// tail W_h pair-major: [d][k/2][ct]{k,k+1}
__device__ float g_hfinal[2 * BATCH * HID];       // final hidden states per direction

__device__ __forceinline__ float sigf(float x) { return 1.0f / (1.0f + __expf(-x)); }
__device__ __forceinline__ float tanh_fast(float x) {
    return 1.0f - 2.0f / (__expf(2.0f * x) + 1.0f);
}

// packed fp32x2 FMA: d.lo += a.lo*b.lo ; d.hi += a.hi*b.hi   (exact fp32 per lane)
__device__ __forceinline__ void ffma2(unsigned long long& d,
                                      unsigned long long a, unsigned long long b) {
    asm("fma.rn.f32x2 %0, %1, %2, %0;" : "+l"(d) : "l"(a), "l"(b));
}
__device__ __forceinline__ float2 ull2f2(unsigned long long v) {
    float2 r; asm("mov.b64 {%0,%1}, %2;" : "=f"(r.x), "=f"(r.y) : "l"(v)); return r;
}
__device__ __forceinline__ unsigned long long fdup(float w) {
    unsigned long long r; asm("mov.b64 %0, {%1,%1};" : "=l"(r) : "f"(w)); return r;
}
__device__ __forceinline__ unsigned long long f2_to_ull(float2 v) {
    unsigned long long r; asm("mov.b64 %0, {%1,%2};" : "=l"(r) : "f"(v.x), "f"(v.y)); return r;
}

// ---------------- kernel 1: Tab[d] = word_emb @ W_d[0:200,:] ----------------
__global__ void __launch_bounds__(512) tab_kernel(const float* __restrict__ emb,
                                                  const float* __restrict__ Wfw,
                                                  const float* __restrict__ Wbw)
{
    __shared__ float es[EMB * 16];   // [k][r] transposed tile, 12.8 KB
    const int d  = blockIdx.y;
    const int v0 = blockIdx.x * 16;
    const float* __restrict__ W = d ? Wbw : Wfw;
    const int tid = threadIdx.x;

    for (int i = tid; i < 16 * EMB; i += 512) {
        int r = i / EMB, k = i % EMB;
        int v = v0 + r;
        es[k * 16 + r] = (v < VOCABP) ? emb[(size_t)v * EMB + k] : 0.0f;
    }
    __syncthreads();

    const int c = tid;   // gate column 0..511
    unsigned long long acc[8];  // 8 packed pairs = 16 rows
#pragma unroll
    for (int p = 0; p < 8; p++) acc[p] = 0ull;

#pragma unroll 4
    for (int k = 0; k < EMB; k++) {
        unsigned long long wd = fdup(__ldg(&W[k * NGATE + c]));
        const ulonglong2* e2 = (const ulonglong2*)&es[k * 16];
        ulonglong2 ea = e2[0], eb = e2[1], ec = e2[2], ed = e2[3];
        ffma2(acc[0], ea.x, wd); ffma2(acc[1], ea.y, wd);
        ffma2(acc[2], eb.x, wd); ffma2(acc[3], eb.y, wd);
        ffma2(acc[4], ec.x, wd); ffma2(acc[5], ec.y, wd);
        ffma2(acc[6], ed.x, wd); ffma2(acc[7], ed.y, wd);
    }

    float* out = &g_tab[((size_t)d * VOCABP + v0) * NGATE + c];
#pragma unroll
    for (int p = 0; p < 8; p++) {
        float2 f = ull2f2(acc[p]);
        if (v0 + 2 * p     < VOCABP) out[(size_t)(2 * p)     * NGATE] = f.x;
        if (v0 + 2 * p + 1 < VOCABP) out[(size_t)(2 * p + 1) * NGATE] = f.y;
    }
}

// ---------------- kernel 2a: cap table (+ bias folded in) ----------------
__global__ void captab_kernel(const float* __restrict__ cemb,
                              const float* __restrict__ Wfw, const float* __restrict__ bfw,
                              const float* __restrict__ Wbw, const float* __restrict__ bbw)
{
    int idx = blockIdx.x * blockDim.x + threadIdx.x;
    if (idx >= 2 * 4 * NGATE) return;
    int d  = idx / (4 * NGATE);
    int ci = (idx / NGATE) & 3;
    int c  = idx % NGATE;
    const float* W = d ? Wbw : Wfw;
    const float* b = d ? bbw : bfw;
    float v = b[c];
#pragma unroll
    for (int j = 0; j < 3; j++) v += cemb[ci * 3 + j] * W[(EMB + j) * NGATE + c];
    g_captab[idx] = v;
}

// ---------------- kernel 2b: tail W_h, pair-major: g_wtail[d][k/2][ct] = {W[k], W[k+1]} ----------------
__global__ void wtail_kernel(const float* __restrict__ Wfw, const float* __restrict__ Wbw)
{
    int idx = blockIdx.x * blockDim.x + threadIdx.x;   // over float2 elements
    if (idx >= 2 * (HID / 2) * TAILC) return;
    int d  = idx / ((HID / 2) * TAILC);
    int k2 = (idx / TAILC) % (HID / 2);
    int ct = idx % TAILC;
    const float* W = d ? Wbw : Wfw;
    g_wtail[idx * 2 + 0] = W[(HOFF + 2 * k2 + 0) * NGATE + SMEM_COLS + ct];
    g_wtail[idx * 2 + 1] = W[(HOFF + 2 * k2 + 1) * NGATE + SMEM_COLS + ct];
}

// ---------------- kernel 3: the recurrent scan (k-split, 16 warps) ----------------
// grid = 128 CTAs: blockIdx.x>>6 = direction, (blockIdx.x&63)*4 = first batch row.
// 512 threads: thread (half = tid>>8, j = tid&255) computes gate columns {j, j+256}
// for 4 batch rows over k in [half*64, half*64+64). Partials staged per half;
// gate update: thread tid owns (row = tid>>7, unit = tid&127).
__global__ void __launch_bounds__(SCAN_T, 1) scan_kernel(const int* __restrict__ words,
                                                         const int* __restrict__ caps,
                                                         const float* __restrict__ Wfw,
                                                         const float* __restrict__ Wbw)
{
    extern __shared__ float sm[];
    float* Ws  = sm;                        // [SMEM_COLS][WPITCH] transposed weights
    float* h_s = Ws + SMEM_COLS * WPITCH;   // [4][HID]
    float* g_s = h_s + 4 * HID;             // [2 halves][4][GPITCH]

    const int tid = threadIdx.x;
    const int d   = blockIdx.x >> 6;
    const int b0  = (blockIdx.x & 63) * 4;
    const float* __restrict__ W = d ? Wbw : Wfw;

    // stage W_h columns [0, SMEM_COLS) transposed: Ws[c][k]  (one-time cost)
    for (int i = tid; i < HID * SMEM_COLS; i += SCAN_T) {
        int k = i / SMEM_COLS, c = i % SMEM_COLS;   // coalesced global read
        Ws[c * WPITCH + k] = W[(HOFF + k) * NGATE + c];
    }
    h_s[tid] = 0.0f;   // 512 = 4*HID exactly

    const int half = tid >> 8;          // k-half: 0 -> [0,64), 1 -> [64,128)
    const int j    = tid & 255;
    const int c0   = j;                 // always in SMEM (384 > 256)
    const int c1   = j + 256;           // tail if j >= 128 (warps 4-7, 12-15)
    const int k0   = half * 64;
    const bool is_tail = (j >= 128);    // warp-uniform
    const float* __restrict__ tabd = &g_tab[(size_t)d * VOCABP * NGATE];
    const float* __restrict__ capd = &g_captab[d * 4 * NGATE];
    const float*  __restrict__ wc0 = &Ws[c0 * WPITCH + k0];
    const float*  __restrict__ wc1 = &Ws[(is_tail ? 0 : c1) * WPITCH + k0];  // dummy for tail
    const float2* __restrict__ wt2 = (const float2*)g_wtail
                                     + d * (HID / 2) * TAILC + (c1 - SMEM_COLS);
    float* gh = g_s + half * 4 * GPITCH;   // this half's staging buffer

    // cap-gate contributions (only half 0 applies x-gate terms)
    float capA0 = 0.f, capA1 = 0.f, capA2 = 0.f, capB0 = 0.f, capB1 = 0.f, capB2 = 0.f;
    if (half == 0) {
        capA0 = __ldg(&capd[0 * NGATE + c0]);
        capA1 = __ldg(&capd[1 * NGATE + c0]);
        capA2 = __ldg(&capd[2 * NGATE + c0]);
        capB0 = __ldg(&capd[0 * NGATE + c1]);
        capB1 = __ldg(&capd[1 * NGATE + c1]);
        capB2 = __ldg(&capd[2 * NGATE + c1]);
    }

    // gate-update mapping: thread tid owns (row, unit)
    const int row = tid >> 7;      // 0..3
    const int u   = tid & 127;
    float cst = 0.0f, hh = 0.0f;

    __syncthreads();

    // index + xg pipeline: widx/cidx hold step-t indices; xa*/xb* hold step-t x-gates
    int widx[4], cidx[4];
    float xa0 = 0.f, xa1 = 0.f, xa2 = 0.f, xa3 = 0.f;
    float xb0 = 0.f, xb1 = 0.f, xb2 = 0.f, xb3 = 0.f;
    {
        int t0 = d ? (TSTEPS - 1) : 0;
#pragma unroll
        for (int r = 0; r < 4; r++) {
            widx[r] = __ldg(&words[(b0 + r) * TSTEPS + t0]);
            cidx[r] = __ldg(&caps [(b0 + r) * TSTEPS + t0]);
        }
        if (half == 0) {
            xa0 = __ldg(&tabd[(size_t)widx[0] * NGATE + c0]);
            xa1 = __ldg(&tabd[(size_t)widx[1] * NGATE + c0]);
            xa2 = __ldg(&tabd[(size_t)widx[2] * NGATE + c0]);
            xa3 = __ldg(&tabd[(size_t)widx[3] * NGATE + c0]);
            xb0 = __ldg(&tabd[(size_t)widx[0] * NGATE + c1]);
            xb1 = __ldg(&tabd[(size_t)widx[1] * NGATE + c1]);
            xb2 = __ldg(&tabd[(size_t)widx[2] * NGATE + c1]);
            xb3 = __ldg(&tabd[(size_t)widx[3] * NGATE + c1]);
            xa0 += (cidx[0] == 0) ? capA0 : ((cidx[0] == 1) ? capA1 : capA2);
            xa1 += (cidx[1] == 0) ? capA0 : ((cidx[1] == 1) ? capA1 : capA2);
            xa2 += (cidx[2] == 0) ? capA0 : ((cidx[2] == 1) ? capA1 : capA2);
            xa3 += (cidx[3] == 0) ? capA0 : ((cidx[3] == 1) ? capA1 : capA2);
            xb0 += (cidx[0] == 0) ? capB0 : ((cidx[0] == 1) ? capB1 : capB2);
            xb1 += (cidx[1] == 0) ? capB0 : ((cidx[1] == 1) ? capB1 : capB2);
            xb2 += (cidx[2] == 0) ? capB0 : ((cidx[2] == 1) ? capB1 : capB2);
            xb3 += (cidx[3] == 0) ? capB0 : ((cidx[3] == 1) ? capB1 : capB2);
        }
    }

    for (int t = 0; t < TSTEPS; t++) {
        // prefetch indices for step t+1 (L1-hot broadcast loads)
        int nwidx[4], ncidx[4];
        {
            int tt = d ? (TSTEPS - 2 - t) : (t + 1);
            if (t + 1 >= TSTEPS) tt = d ? 0 : (TSTEPS - 1);   // clamp: values unused
#pragma unroll
            for (int r = 0; r < 4; r++) {
                nwidx[r] = __ldg(&words[(b0 + r) * TSTEPS + tt]);
                ncidx[r] = __ldg(&caps [(b0 + r) * TSTEPS + tt]);
            }
        }

        // recurrent partial GEMM: 2 cols x 4 rows, k in [k0, k0+64), f32x2 k-pairs
        unsigned long long A0 = 0ull, A1 = 0ull, A2 = 0ull, A3 = 0ull;   // col c0
        unsigned long long E0 = 0ull, E1 = 0ull, E2 = 0ull, E3 = 0ull;   // col c1
        if (!is_tail) {
#pragma unroll 8
            for (int kk = 0; kk < 64; kk += 4) {
                ulonglong2 w0 = *(const ulonglong2*)&wc0[kk];   // LDS.128: k-pairs
                ulonglong2 w1 = *(const ulonglong2*)&wc1[kk];
                ulonglong2 h0 = *(const ulonglong2*)&h_s[0 * HID + k0 + kk];  // broadcast
                ulonglong2 h1 = *(const ulonglong2*)&h_s[1 * HID + k0 + kk];
                ulonglong2 h2 = *(const ulonglong2*)&h_s[2 * HID + k0 + kk];
                ulonglong2 h3 = *(const ulonglong2*)&h_s[3 * HID + k0 + kk];
                ffma2(A0, h0.x, w0.x); ffma2(A0, h0.y, w0.y);
                ffma2(A1, h1.x, w0.x); ffma2(A1, h1.y, w0.y);
                ffma2(A2, h2.x, w0.x); ffma2(A2, h2.y, w0.y);
                ffma2(A3, h3.x, w0.x); ffma2(A3, h3.y, w0.y);
                ffma2(E0, h0.x, w1.x); ffma2(E0, h0.y, w1.y);
                ffma2(E1, h1.x, w1.x); ffma2(E1, h1.y, w1.y);
                ffma2(E2, h2.x, w1.x); ffma2(E2, h2.y, w1.y);
                ffma2(E3, h3.x, w1.x); ffma2(E3, h3.y, w1.y);
            }
        } else {
            // col c1 streamed from L2: pair-major float2 -> dense LDG.64 per lane
#pragma unroll 8
            for (int kk = 0; kk < 64; kk += 4) {
                ulonglong2 w0 = *(const ulonglong2*)&wc0[kk];
                float2 t0 = __ldg(&wt2[((k0 + kk) >> 1) * TAILC]);
                float2 t1 = __ldg(&wt2[(((k0 + kk) >> 1) + 1) * TAILC]);
                unsigned long long w1x = f2_to_ull(t0);
                unsigned long long w1y = f2_to_ull(t1);
                ulonglong2 h0 = *(const ulonglong2*)&h_s[0 * HID + k0 + kk];
                ulonglong2 h1 = *(const ulonglong2*)&h_s[1 * HID + k0 + kk];
                ulonglong2 h2 = *(const ulonglong2*)&h_s[2 * HID + k0 + kk];
                ulonglong2 h3 = *(const ulonglong2*)&h_s[3 * HID + k0 + kk];
                ffma2(A0, h0.x, w0.x); ffma2(A0, h0.y, w0.y);
                ffma2(A1, h1.x, w0.x); ffma2(A1, h1.y, w0.y);
                ffma2(A2, h2.x, w0.x); ffma2(A2, h2.y, w0.y);
                ffma2(A3, h3.x, w0.x); ffma2(A3, h3.y, w0.y);
                ffma2(E0, h0.x, w1x); ffma2(E0, h0.y, w1y);
                ffma2(E1, h1.x, w1x); ffma2(E1, h1.y, w1y);
                ffma2(E2, h2.x, w1x); ffma2(E2, h2.y, w1y);
                ffma2(E3, h3.x, w1x); ffma2(E3, h3.y, w1y);
            }
        }
        {
            float2 f;
            f = ull2f2(A0); gh[0 * GPITCH + c0] = f.x + f.y + xa0;
            f = ull2f2(A1); gh[1 * GPITCH + c0] = f.x + f.y + xa1;
            f = ull2f2(A2); gh[2 * GPITCH + c0] = f.x + f.y + xa2;
            f = ull2f2(A3); gh[3 * GPITCH + c0] = f.x + f.y + xa3;
            f = ull2f2(E0); gh[0 * GPITCH + c1] = f.x + f.y + xb0;
            f = ull2f2(E1); gh[1 * GPITCH + c1] = f.x + f.y + xb1;
            f = ull2f2(E2); gh[2 * GPITCH + c1] = f.x + f.y + xb2;
            f = ull2f2(E3); gh[3 * GPITCH + c1] = f.x + f.y + xb3;
        }

        // issue x-gate gathers for step t+1 NOW (consumed after two barriers + k-loop)
        if (half == 0 && t + 1 < TSTEPS) {
            xa0 = __ldg(&tabd[(size_t)nwidx[0] * NGATE + c0]);
            xa1 = __ldg(&tabd[(size_t)nwidx[1] * NGATE + c0]);
            xa2 = __ldg(&tabd[(size_t)nwidx[2] * NGATE + c0]);
            xa3 = __ldg(&tabd[(size_t)nwidx[3] * NGATE + c0]);
            xb0 = __ldg(&tabd[(size_t)nwidx[0] * NGATE + c1]);
            xb1 = __ldg(&tabd[(size_t)nwidx[1] * NGATE + c1]);
            xb2 = __ldg(&tabd[(size_t)nwidx[2] * NGATE + c1]);
            xb3 = __ldg(&tabd[(size_t)nwidx[3] * NGATE + c1]);
            xa0 += (ncidx[0] == 0) ? capA0 : ((ncidx[0] == 1) ? capA1 : capA2);
            xa1 += (ncidx[1] == 0) ? capA0 : ((ncidx[1] == 1) ? capA1 : capA2);
            xa2 += (ncidx[2] == 0) ? capA0 : ((ncidx[2] == 1) ? capA1 : capA2);
            xa3 += (ncidx[3] == 0) ? capA0 : ((ncidx[3] == 1) ? capA1 : capA2);
            xb0 += (ncidx[0] == 0) ? capB0 : ((ncidx[0] == 1) ? capB1 : capB2);
            xb1 += (ncidx[1] == 0) ? capB0 : ((ncidx[1] == 1) ? capB1 : capB2);
            xb2 += (ncidx[2] == 0) ? capB0 : ((ncidx[2] == 1) ? capB1 : capB2);
            xb3 += (ncidx[3] == 0) ? capB0 : ((ncidx[3] == 1) ? capB1 : capB2);
        }
#pragma unroll
        for (int r = 0; r < 4; r++) { widx[r] = nwidx[r]; cidx[r] = ncidx[r]; }

        __syncthreads();

        // gate update: thread tid owns (row, u); sums the two k-half partials
        {
            float gi = g_s[row * GPITCH + u]           + g_s[4 * GPITCH + row * GPITCH + u];
            float gj = g_s[row * GPITCH + u + HID]     + g_s[4 * GPITCH + row * GPITCH + u + HID];
            float gf = g_s[row * GPITCH + u + 2 * HID] + g_s[4 * GPITCH + row * GPITCH + u + 2 * HID];
            float go = g_s[row * GPITCH + u + 3 * HID] + g_s[4 * GPITCH + row * GPITCH + u + 3 * HID];
            cst = sigf(gf + 1.0f) * cst + sigf(gi) * tanh_fast(gj);
            hh  = sigf(go) * tanh_fast(cst);
            h_s[row * HID + u] = hh;
        }
        __syncthreads();
    }

    g_hfinal[((d * BATCH) + (b0 + row)) * HID + u] = hh;
}

// ---------------- kernel 4: dense head ----------------
__global__ void __launch_bounds__(256) dense_kernel(const float* __restrict__ W1,
                                                    const float* __restrict__ b1,
                                                    const float* __restrict__ W2,
                                                    const float* __restrict__ b2,
                                                    float* __restrict__ out)
{
    __shared__ float red[256];
    __shared__ float d1[DENSE];
    const int b = blockIdx.x, t = threadIdx.x;
    const int j = t & 63, q = t >> 6;
    const float* xin = (q < 2) ? &g_hfinal[b * HID + q * 64]
                               : &g_hfinal[(BATCH + b) * HID + (q - 2) * 64];
    const float* w   = &W1[(q * 64) * DENSE + j];
    float acc = 0.0f;
#pragma unroll 8
    for (int i = 0; i < 64; i++) acc += xin[i] * w[i * DENSE];
    red[t] = acc;
    __syncthreads();
    if (t < DENSE) {
        float a = red[t] + red[t + 64] + red[t + 128] + red[t + 192] + b1[t];
        d1[t] = (a > 0.0f) ? a : (__expf(a) - 1.0f);   // elu
    }
    __syncthreads();
    if (t < NC) {
        float a = b2[t];
#pragma unroll
        for (int k = 0; k < DENSE; k++) a += d1[k] * W2[k * NC + t];
        out[b * NC + t] = 1.0f / (1.0f + __expf(-a));  // sigmoid
    }
}

// ---------------- launch ----------------
extern "C" void kernel_launch(void* const* d_in, const int* in_sizes, int n_in,
                              void* d_out, int out_size)
{
    const int*   words = (const int*)  d_in[0];
    const int*   caps  = (const int*)  d_in[1];
    const float* emb   = (const float*)d_in[2];
    const float* cemb  = (const float*)d_in[3];
    const float* Wfw   = (const float*)d_in[4];
    const float* bfw   = (const float*)d_in[5];
    const float* Wbw   = (const float*)d_in[6];
    const float* bbw   = (const float*)d_in[7];
    const float* W1    = (const float*)d_in[8];
    const float* b1    = (const float*)d_in[9];
    const float* W2    = (const float*)d_in[10];
    const float* b2    = (const float*)d_in[11];
    float* out = (float*)d_out;

    cudaFuncSetAttribute(scan_kernel, cudaFuncAttributeMaxDynamicSharedMemorySize,
                         SCAN_SMEM_BYTES);

    wtail_kernel<<<(2 * (HID / 2) * TAILC + 511) / 512, 512>>>(Wfw, Wbw);
    captab_kernel<<<8, 512>>>(cemb, Wfw, bfw, Wbw, bbw);
    tab_kernel<<<dim3((VOCABP + 15) / 16, 2), 512>>>(emb, Wfw, Wbw);
    scan_kernel<<<128, SCAN_T, SCAN_SMEM_BYTES>>>(words, caps, Wfw, Wbw);
    dense_kernel<<<BATCH, 256>>>(W1, b1, W2, b2, out);
}